// round 13
// baseline (speedup 1.0000x reference)
#include <cuda_runtime.h>

// CosinLoss fully fused, single kernel: loss = mean_i(1 - cos(pc_i, aug_i)).
// N=16384 rows, D=1024 fp32 (128 MiB streamed).
// Main loop: 4 rows per 256-thread CTA (64 thr/row, 4 float4/tensor/thread ->
// MLP_p1=8), grid 4096, __ldcs streaming loads. __launch_bounds__(256,8) forces
// regs<=32 so 8 CTAs/SM (full 64-warp occupancy).
//
// Epilogue: each worker CTA issues ONE red.relaxed.gpu u64 add of a packed word
// (1<<50 | fixed_point_partial); row loss in [0,2] so the partial is always
// non-negative (no bias needed); grand total < 8*4096*2^32 = 2^47 < 2^50.
// A poller CTA (last block, starts in the final wave) acquire-polls the word
// until count==GRID1; the low 50 bits then hold the exact integer total (same-
// address modification order). Integer adds -> bit-deterministic.

#define CL_N   16384
#define CL_D   1024
#define CL_EPS 1e-12f
#define GRID1  4096
#define CNT_SHIFT 50
#define SUM_MASK  ((1ULL << CNT_SHIFT) - 1ULL)
#define FP_SCALE  4294967296.0    // 2^32

__device__ unsigned long long g_accum = 0ULL;

__global__ __launch_bounds__(256, 8)
void cos_loss_fused(const float* __restrict__ pc, const float* __restrict__ aug,
                    float* __restrict__ out) {
    // ---------------- Poller CTA (last block; scheduled in the final wave) ----------------
    if (blockIdx.x == GRID1) {
        if (threadIdx.x == 0) {
            unsigned long long v;
            while (true) {
                asm volatile("ld.acquire.gpu.global.b64 %0, [%1];"
                             : "=l"(v) : "l"(&g_accum) : "memory");
                if ((v >> CNT_SHIFT) == GRID1) break;
                __nanosleep(64);
            }
            double sum = (double)(v & SUM_MASK) * (1.0 / FP_SCALE);
            out[0] = (float)(sum * (1.0 / (double)CL_N));
            // Reset for next graph replay (all adds for this launch are in v).
            asm volatile("st.global.cg.b64 [%0], %1;" :: "l"(&g_accum), "l"(0ULL) : "memory");
        }
        return;
    }

    // ---------------- Worker CTAs ----------------
    const int t    = threadIdx.x;
    const int wid  = t >> 5;        // 0..7; warps 2r,2r+1 own row r
    const int lane = t & 31;
    const int rsub = t >> 6;        // 0..3: row within CTA
    const int ct   = t & 63;        // thread index within row (64 thr/row)
    const size_t row = (size_t)blockIdx.x * 4 + rsub;

    const float4* __restrict__ p4 = reinterpret_cast<const float4*>(pc  + row * CL_D);
    const float4* __restrict__ a4 = reinterpret_cast<const float4*>(aug + row * CL_D);

    // 8 outstanding LDG.128 per thread, streaming hint.
    float4 p0 = __ldcs(&p4[ct      ]);
    float4 p1 = __ldcs(&p4[ct +  64]);
    float4 p2 = __ldcs(&p4[ct + 128]);
    float4 p3 = __ldcs(&p4[ct + 192]);
    float4 a0 = __ldcs(&a4[ct      ]);
    float4 a1 = __ldcs(&a4[ct +  64]);
    float4 a2 = __ldcs(&a4[ct + 128]);
    float4 a3 = __ldcs(&a4[ct + 192]);

    float dot = p0.x*a0.x + p0.y*a0.y + p0.z*a0.z + p0.w*a0.w
              + p1.x*a1.x + p1.y*a1.y + p1.z*a1.z + p1.w*a1.w
              + p2.x*a2.x + p2.y*a2.y + p2.z*a2.z + p2.w*a2.w
              + p3.x*a3.x + p3.y*a3.y + p3.z*a3.z + p3.w*a3.w;
    float npp = p0.x*p0.x + p0.y*p0.y + p0.z*p0.z + p0.w*p0.w
              + p1.x*p1.x + p1.y*p1.y + p1.z*p1.z + p1.w*p1.w
              + p2.x*p2.x + p2.y*p2.y + p2.z*p2.z + p2.w*p2.w
              + p3.x*p3.x + p3.y*p3.y + p3.z*p3.z + p3.w*p3.w;
    float naa = a0.x*a0.x + a0.y*a0.y + a0.z*a0.z + a0.w*a0.w
              + a1.x*a1.x + a1.y*a1.y + a1.z*a1.z + a1.w*a1.w
              + a2.x*a2.x + a2.y*a2.y + a2.z*a2.z + a2.w*a2.w
              + a3.x*a3.x + a3.y*a3.y + a3.z*a3.z + a3.w*a3.w;

    #pragma unroll
    for (int off = 16; off > 0; off >>= 1) {
        dot += __shfl_down_sync(0xFFFFFFFFu, dot, off);
        npp += __shfl_down_sync(0xFFFFFFFFu, npp, off);
        naa += __shfl_down_sync(0xFFFFFFFFu, naa, off);
    }

    __shared__ float s_dot[8], s_npp[8], s_naa[8];
    if (lane == 0) {
        s_dot[wid] = dot;
        s_npp[wid] = npp;
        s_naa[wid] = naa;
    }
    __syncthreads();

    // Warp 0, lanes 0..7: slot pairs (2r, 2r+1) belong to row r.
    if (wid == 0 && lane < 8) {
        dot = s_dot[lane];
        npp = s_npp[lane];
        naa = s_naa[lane];
        dot += __shfl_xor_sync(0x000000FFu, dot, 1);
        npp += __shfl_xor_sync(0x000000FFu, npp, 1);
        naa += __shfl_xor_sync(0x000000FFu, naa, 1);

        float loss = 0.0f;
        if ((lane & 1) == 0) {
            float np_ = fmaxf(sqrtf(npp), CL_EPS);
            float na_ = fmaxf(sqrtf(naa), CL_EPS);
            loss = 1.0f - dot / (np_ * na_);
        }
        loss += __shfl_down_sync(0x000000FFu, loss, 4);
        loss += __shfl_down_sync(0x000000FFu, loss, 2);

        if (lane == 0) {
            // Fixed-point encode; per-CTA partial in [0,8] -> fp < 2^35.
            unsigned long long fp =
                (unsigned long long)((double)loss * FP_SCALE + 0.5);
            unsigned long long word = (1ULL << CNT_SHIFT) | fp;
            // No-return reduction: worker never waits on an L2 round-trip.
            asm volatile("red.relaxed.gpu.global.add.u64 [%0], %1;"
                         :: "l"(&g_accum), "l"(word) : "memory");
        }
    }
}

extern "C" void kernel_launch(void* const* d_in, const int* in_sizes, int n_in,
                              void* d_out, int out_size) {
    const float* pc  = (const float*)d_in[0];
    const float* aug = (const float*)d_in[1];
    float* out = (float*)d_out;

    cos_loss_fused<<<GRID1 + 1, 256>>>(pc, aug, out);
}

// round 14
// speedup vs baseline: 1.2079x; 1.2079x over previous
#include <cuda_runtime.h>

// CosinLoss: loss = mean_i(1 - cos(pc_i, aug_i)). N=16384, D=1024 fp32 (128 MiB).
// K1: 4 rows per 256-thread CTA (64 thr/row, 4 float4/tensor/thread -> MLP_p1=8),
//     grid 4096, __ldcs streaming, launch_bounds(256,8) -> regs<=32, 8 CTAs/SM.
//     Epilogue: ONE red.relaxed.gpu.add.u64 of the fixed-point CTA partial.
//     No return wait, no poller, no fences -> kernel retires immediately; REDs
//     drain asynchronously. Integer adds -> bit-deterministic (2^-32 quantization).
// K2: 1 warp. Inter-kernel ordering guarantees all K1 REDs are visible. Reads the
//     single u64 total, writes the mean, resets the accumulator for graph replay.

#define CL_N   16384
#define CL_D   1024
#define CL_EPS 1e-12f
#define GRID1  4096
#define FP_SCALE  4294967296.0    // 2^32; total < 4096*8*2^32 = 2^47

__device__ unsigned long long g_accum = 0ULL;

__global__ __launch_bounds__(256, 8)
void cos_loss_main(const float* __restrict__ pc, const float* __restrict__ aug) {
    const int t    = threadIdx.x;
    const int wid  = t >> 5;        // 0..7; warps 2r,2r+1 own row r
    const int lane = t & 31;
    const int rsub = t >> 6;        // 0..3: row within CTA
    const int ct   = t & 63;        // thread index within row (64 thr/row)
    const size_t row = (size_t)blockIdx.x * 4 + rsub;

    const float4* __restrict__ p4 = reinterpret_cast<const float4*>(pc  + row * CL_D);
    const float4* __restrict__ a4 = reinterpret_cast<const float4*>(aug + row * CL_D);

    // 8 outstanding LDG.128 per thread, streaming hint.
    float4 p0 = __ldcs(&p4[ct      ]);
    float4 p1 = __ldcs(&p4[ct +  64]);
    float4 p2 = __ldcs(&p4[ct + 128]);
    float4 p3 = __ldcs(&p4[ct + 192]);
    float4 a0 = __ldcs(&a4[ct      ]);
    float4 a1 = __ldcs(&a4[ct +  64]);
    float4 a2 = __ldcs(&a4[ct + 128]);
    float4 a3 = __ldcs(&a4[ct + 192]);

    float dot = p0.x*a0.x + p0.y*a0.y + p0.z*a0.z + p0.w*a0.w
              + p1.x*a1.x + p1.y*a1.y + p1.z*a1.z + p1.w*a1.w
              + p2.x*a2.x + p2.y*a2.y + p2.z*a2.z + p2.w*a2.w
              + p3.x*a3.x + p3.y*a3.y + p3.z*a3.z + p3.w*a3.w;
    float npp = p0.x*p0.x + p0.y*p0.y + p0.z*p0.z + p0.w*p0.w
              + p1.x*p1.x + p1.y*p1.y + p1.z*p1.z + p1.w*p1.w
              + p2.x*p2.x + p2.y*p2.y + p2.z*p2.z + p2.w*p2.w
              + p3.x*p3.x + p3.y*p3.y + p3.z*p3.z + p3.w*p3.w;
    float naa = a0.x*a0.x + a0.y*a0.y + a0.z*a0.z + a0.w*a0.w
              + a1.x*a1.x + a1.y*a1.y + a1.z*a1.z + a1.w*a1.w
              + a2.x*a2.x + a2.y*a2.y + a2.z*a2.z + a2.w*a2.w
              + a3.x*a3.x + a3.y*a3.y + a3.z*a3.z + a3.w*a3.w;

    #pragma unroll
    for (int off = 16; off > 0; off >>= 1) {
        dot += __shfl_down_sync(0xFFFFFFFFu, dot, off);
        npp += __shfl_down_sync(0xFFFFFFFFu, npp, off);
        naa += __shfl_down_sync(0xFFFFFFFFu, naa, off);
    }

    __shared__ float s_dot[8], s_npp[8], s_naa[8];
    if (lane == 0) {
        s_dot[wid] = dot;
        s_npp[wid] = npp;
        s_naa[wid] = naa;
    }
    __syncthreads();

    // Warp 0, lanes 0..7: slot pairs (2r, 2r+1) belong to row r.
    if (wid == 0 && lane < 8) {
        dot = s_dot[lane];
        npp = s_npp[lane];
        naa = s_naa[lane];
        dot += __shfl_xor_sync(0x000000FFu, dot, 1);
        npp += __shfl_xor_sync(0x000000FFu, npp, 1);
        naa += __shfl_xor_sync(0x000000FFu, naa, 1);

        float loss = 0.0f;
        if ((lane & 1) == 0) {
            float np_ = fmaxf(sqrtf(npp), CL_EPS);
            float na_ = fmaxf(sqrtf(naa), CL_EPS);
            loss = 1.0f - dot / (np_ * na_);
        }
        loss += __shfl_down_sync(0x000000FFu, loss, 4);
        loss += __shfl_down_sync(0x000000FFu, loss, 2);

        if (lane == 0) {
            // Fixed-point encode; per-CTA partial in [0,8] -> fp < 2^35.
            unsigned long long fp =
                (unsigned long long)((double)loss * FP_SCALE + 0.5);
            // Fire-and-forget reduction; no L2 round-trip on the critical path.
            asm volatile("red.relaxed.gpu.global.add.u64 [%0], %1;"
                         :: "l"(&g_accum), "l"(fp) : "memory");
        }
    }
}

// K2: read the single accumulated word, finish, and reset for graph replay.
__global__ __launch_bounds__(32)
void cos_loss_finish(float* __restrict__ out) {
    if (threadIdx.x == 0) {
        unsigned long long v = __ldcg(&g_accum);
        double sum = (double)v * (1.0 / FP_SCALE);
        out[0] = (float)(sum * (1.0 / (double)CL_N));
        asm volatile("st.global.cg.b64 [%0], %1;" :: "l"(&g_accum), "l"(0ULL) : "memory");
    }
}

extern "C" void kernel_launch(void* const* d_in, const int* in_sizes, int n_in,
                              void* d_out, int out_size) {
    const float* pc  = (const float*)d_in[0];
    const float* aug = (const float*)d_in[1];
    float* out = (float*)d_out;

    cos_loss_main<<<GRID1, 256>>>(pc, aug);
    cos_loss_finish<<<1, 32>>>(out);
}